// round 14
// baseline (speedup 1.0000x reference)
#include <cuda_runtime.h>
#include <cstdint>

// Fused separable bicubic downscale (scale = 1/4 exactly).
// Key structural fact: with scale 0.25, u - left == 8.5 for every output row,
// so all rows of w_h (and of w_w) are the SAME weight vector. Weights are
// shared; only index tables vary (boundary mirroring).
//
// x: (24, 1080, 1920) f32 -> out: (24, 270, 480) f32
// CTA = (bc, strip of 6 output rows), 480 threads, thread t = float4 column.
// Phase V: dense scatter table (w_acc) built from w_h/idx_h; one sweep over
//          unique input rows, depth-2 prefetch, 6 float4 accumulators.
// Phase H: shared weight vector + int16 staged indices, conflict-free
//          partitioned smem gather.

#define H_IN     1080
#define W_IN     1920
#define OH_OUT   270
#define OW_OUT   480
#define R_TILE   6
#define MAXP     18
#define NT       480
#define SPAN_MAX 64
#define RPAD     8
#define TPAD     (MAXP + 1)     // 19

__global__ __launch_bounds__(NT, 3)
void bicubic_fused5(const float* __restrict__ x,
                    const float* __restrict__ w_h,
                    const int*   __restrict__ idx_h,
                    const float* __restrict__ w_w,
                    const int*   __restrict__ idx_w,
                    float* __restrict__ out,
                    int Ph, int Pw, int nTiles)
{
    // dynamic smem:
    //   s_interm : R_TILE * W_IN floats     (46080 B)
    //   s_tidx   : OW_OUT * TPAD int16      (18240 B)
    extern __shared__ float smemRaw[];
    float* s_interm = smemRaw;
    short* s_tidx   = (short*)(s_interm + R_TILE * W_IN);

    __shared__ float s_wacc[SPAN_MAX * RPAD];   // dense vertical scatter table
    __shared__ float s_wwv[MAXP];               // shared horizontal weights
    __shared__ int   s_imin, s_imax;

    const int tid = threadIdx.x;
    const int bc  = blockIdx.x / nTiles;
    const int oh0 = (blockIdx.x % nTiles) * R_TILE;    // OH % R_TILE == 0

    if (tid == 0) { s_imin = 0x7fffffff; s_imax = 0; }
    if (tid < Pw) s_wwv[tid] = w_w[tid];               // row 0 == every row
    for (int i = tid; i < SPAN_MAX * RPAD; i += NT) s_wacc[i] = 0.f;
    __syncthreads();

    // ---- stage horizontal index table (coalesced LDG -> padded int16) ----
    const int nTapW = OW_OUT * Pw;
    for (int i = tid; i < nTapW; i += NT) {
        int row = i / Pw, q = i - row * Pw;
        int iq = idx_w[i];
        s_tidx[row * TPAD + q] = (short)((iq & 3) * (W_IN / 4) + (iq >> 2));
    }

    // ---- vertical span + dense contribution table ----
    const int nTapV = R_TILE * Ph;
    for (int i = tid; i < nTapV; i += NT) {
        int r = i / Ph, p = i - r * Ph;
        int iv = idx_h[(oh0 + r) * Ph + p];
        atomicMin(&s_imin, iv);
        atomicMax(&s_imax, iv);
    }
    __syncthreads();
    const int i0   = s_imin;
    const int span = s_imax - i0 + 1;                  // <= ~38

    for (int i = tid; i < nTapV; i += NT) {
        int r = i / Ph, p = i - r * Ph;
        int   iv = idx_h[(oh0 + r) * Ph + p];
        float wv = w_h[(oh0 + r) * Ph + p];
        atomicAdd(&s_wacc[(iv - i0) * RPAD + r], wv);
    }
    __syncthreads();

    // ---- Phase V: one sweep over unique rows, depth-2 prefetch ----
    const float4* xp = (const float4*)(x + (size_t)bc * H_IN * W_IN)
                     + (size_t)i0 * (W_IN / 4) + tid;
    float4 acc[R_TILE];
    #pragma unroll
    for (int r = 0; r < R_TILE; r++) acc[r] = make_float4(0.f, 0.f, 0.f, 0.f);

    float4 v0 = __ldg(xp);
    float4 v1 = __ldg(xp + (size_t)min(1, span - 1) * (W_IN / 4));
    for (int i = 0; i < span; i++) {
        float4 vn = __ldg(xp + (size_t)min(i + 2, span - 1) * (W_IN / 4));
        float4 w03 = *(const float4*)&s_wacc[i * RPAD + 0];
        float4 w47 = *(const float4*)&s_wacc[i * RPAD + 4];
        float wr[R_TILE] = { w03.x, w03.y, w03.z, w03.w, w47.x, w47.y };
        #pragma unroll
        for (int r = 0; r < R_TILE; r++) {
            acc[r].x += wr[r] * v0.x;
            acc[r].y += wr[r] * v0.y;
            acc[r].z += wr[r] * v0.z;
            acc[r].w += wr[r] * v0.w;
        }
        v0 = v1;
        v1 = vn;
    }

    // store partitioned: column c = 4*tid + j -> s[j*480 + tid]
    #pragma unroll
    for (int r = 0; r < R_TILE; r++) {
        float* sd = s_interm + r * W_IN;
        sd[0 * (W_IN / 4) + tid] = acc[r].x;
        sd[1 * (W_IN / 4) + tid] = acc[r].y;
        sd[2 * (W_IN / 4) + tid] = acc[r].z;
        sd[3 * (W_IN / 4) + tid] = acc[r].w;
    }
    __syncthreads();

    // ---- Phase H: shared weights + int16 indices, partitioned gather ----
    const int ow = tid;
    int iqT[MAXP];
    #pragma unroll 6
    for (int q = 0; q < Pw; q++) {
        iqT[q] = (int)s_tidx[ow * TPAD + q];
    }

    float* outp = out + ((size_t)bc * OH_OUT + oh0) * OW_OUT + ow;
    #pragma unroll
    for (int r = 0; r < R_TILE; r++) {
        const float* srow = s_interm + r * W_IN;
        float a = 0.f;
        #pragma unroll 6
        for (int q = 0; q < Pw; q++) {
            a += s_wwv[q] * srow[iqT[q]];
        }
        outp[r * OW_OUT] = a;
    }
}

extern "C" void kernel_launch(void* const* d_in, const int* in_sizes, int n_in,
                              void* d_out, int out_size)
{
    const float* x     = (const float*)d_in[0];
    const float* w_h   = (const float*)d_in[1];
    const int*   idx_h = (const int*)  d_in[2];
    const float* w_w   = (const float*)d_in[3];
    const int*   idx_w = (const int*)  d_in[4];
    float* out = (float*)d_out;

    const int BC = in_sizes[0] / (H_IN * W_IN);   // 24
    const int Ph = in_sizes[1] / OH_OUT;          // <= 18
    const int Pw = in_sizes[3] / OW_OUT;          // <= 18

    const int nTiles = OH_OUT / R_TILE;           // 45
    size_t smem = (size_t)R_TILE * W_IN * sizeof(float)
                + (size_t)OW_OUT * TPAD * sizeof(short);

    cudaFuncSetAttribute(bicubic_fused5,
                         cudaFuncAttributeMaxDynamicSharedMemorySize,
                         (int)(70 * 1024));

    dim3 grid(BC * nTiles);                       // 1080
    bicubic_fused5<<<grid, NT, smem>>>(
        x, w_h, idx_h, w_w, idx_w, out, Ph, Pw, nTiles);
}

// round 15
// speedup vs baseline: 1.3304x; 1.3304x over previous
#include <cuda_runtime.h>
#include <cstdint>

// Fused separable bicubic downscale (scale = 1/4: all rows of w_w share one
// weight vector; all rows of w_h likewise — only index tables vary).
// x: (24, 1080, 1920) f32 -> out: (24, 270, 480) f32
//
// CTA = (bc, strip of 6 output rows), 480 threads, thread t = float4 column.
// Phase V: dense scatter table w_acc[input_row][r]; single sweep over unique
//          input rows with DEPTH-3 prefetch; 6 float4 accumulators.
// Phase H: weights+indices hoisted to registers, conflict-free partitioned
//          smem gather.

#define H_IN     1080
#define W_IN     1920
#define OH_OUT   270
#define OW_OUT   480
#define R_TILE   6
#define MAXP     18
#define NT       480
#define SPAN_MAX 64
#define RPAD     8
#define TPAD     (MAXP + 1)     // 19

__global__ __launch_bounds__(NT, 2)
void bicubic_fused6(const float* __restrict__ x,
                    const float* __restrict__ w_h,
                    const int*   __restrict__ idx_h,
                    const float* __restrict__ w_w,
                    const int*   __restrict__ idx_w,
                    float* __restrict__ out,
                    int Ph, int Pw, int nTiles)
{
    // dynamic smem:
    //   s_interm : R_TILE * W_IN floats     (46080 B)
    //   s_tidx   : OW_OUT * TPAD int16      (18240 B)
    extern __shared__ float smemRaw[];
    float* s_interm = smemRaw;
    short* s_tidx   = (short*)(s_interm + R_TILE * W_IN);

    __shared__ float s_wacc[SPAN_MAX * RPAD];
    __shared__ float s_wwv[MAXP];
    __shared__ int   s_imin, s_imax;

    const int tid = threadIdx.x;
    const int bc  = blockIdx.x / nTiles;
    const int oh0 = (blockIdx.x % nTiles) * R_TILE;    // OH % R_TILE == 0

    if (tid == 0) { s_imin = 0x7fffffff; s_imax = 0; }
    if (tid < Pw) s_wwv[tid] = w_w[tid];               // row 0 == every row
    for (int i = tid; i < SPAN_MAX * RPAD; i += NT) s_wacc[i] = 0.f;
    __syncthreads();

    // ---- stage horizontal index table (coalesced LDG -> padded int16) ----
    const int nTapW = OW_OUT * Pw;
    for (int i = tid; i < nTapW; i += NT) {
        int row = i / Pw, q = i - row * Pw;
        int iq = idx_w[i];
        s_tidx[row * TPAD + q] = (short)((iq & 3) * (W_IN / 4) + (iq >> 2));
    }

    // ---- vertical span + dense contribution table ----
    const int nTapV = R_TILE * Ph;
    for (int i = tid; i < nTapV; i += NT) {
        int r = i / Ph, p = i - r * Ph;
        int iv = idx_h[(oh0 + r) * Ph + p];
        atomicMin(&s_imin, iv);
        atomicMax(&s_imax, iv);
    }
    __syncthreads();
    const int i0   = s_imin;
    const int span = s_imax - i0 + 1;                  // <= ~38

    for (int i = tid; i < nTapV; i += NT) {
        int r = i / Ph, p = i - r * Ph;
        int   iv = idx_h[(oh0 + r) * Ph + p];
        float wv = w_h[(oh0 + r) * Ph + p];
        atomicAdd(&s_wacc[(iv - i0) * RPAD + r], wv);
    }
    __syncthreads();

    // ---- Phase V: one sweep over unique rows, depth-3 prefetch ----
    const float4* xp = (const float4*)(x + (size_t)bc * H_IN * W_IN)
                     + (size_t)i0 * (W_IN / 4) + tid;
    const int lastOfs = (span - 1) * (W_IN / 4);

    float4 acc[R_TILE];
    #pragma unroll
    for (int r = 0; r < R_TILE; r++) acc[r] = make_float4(0.f, 0.f, 0.f, 0.f);

    float4 v0 = __ldg(xp);
    float4 v1 = __ldg(xp + min(1 * (W_IN / 4), lastOfs));
    float4 v2 = __ldg(xp + min(2 * (W_IN / 4), lastOfs));

    for (int i = 0; i < span; i++) {
        float4 vn = __ldg(xp + min((i + 3) * (W_IN / 4), lastOfs));
        float4 w03 = *(const float4*)&s_wacc[i * RPAD + 0];
        float4 w47 = *(const float4*)&s_wacc[i * RPAD + 4];
        float wr[R_TILE] = { w03.x, w03.y, w03.z, w03.w, w47.x, w47.y };
        #pragma unroll
        for (int r = 0; r < R_TILE; r++) {
            acc[r].x += wr[r] * v0.x;
            acc[r].y += wr[r] * v0.y;
            acc[r].z += wr[r] * v0.z;
            acc[r].w += wr[r] * v0.w;
        }
        v0 = v1; v1 = v2; v2 = vn;
    }

    // store partitioned: column c = 4*tid + j -> s[j*480 + tid]
    #pragma unroll
    for (int r = 0; r < R_TILE; r++) {
        float* sd = s_interm + r * W_IN;
        sd[0 * (W_IN / 4) + tid] = acc[r].x;
        sd[1 * (W_IN / 4) + tid] = acc[r].y;
        sd[2 * (W_IN / 4) + tid] = acc[r].z;
        sd[3 * (W_IN / 4) + tid] = acc[r].w;
    }
    __syncthreads();

    // ---- hoist taps into registers (accs are dead now) ----
    const int ow = tid;
    float wq[MAXP];
    int   iqT[MAXP];
    #pragma unroll 6
    for (int q = 0; q < Pw; q++) {
        wq[q]  = s_wwv[q];                      // broadcast LDS
        iqT[q] = (int)s_tidx[ow * TPAD + q];
    }

    // ---- Phase H: register taps, conflict-free partitioned gather ----
    float* outp = out + ((size_t)bc * OH_OUT + oh0) * OW_OUT + ow;
    #pragma unroll
    for (int r = 0; r < R_TILE; r++) {
        const float* srow = s_interm + r * W_IN;
        float a = 0.f;
        #pragma unroll 6
        for (int q = 0; q < Pw; q++) {
            a += wq[q] * srow[iqT[q]];
        }
        outp[r * OW_OUT] = a;
    }
}

extern "C" void kernel_launch(void* const* d_in, const int* in_sizes, int n_in,
                              void* d_out, int out_size)
{
    const float* x     = (const float*)d_in[0];
    const float* w_h   = (const float*)d_in[1];
    const int*   idx_h = (const int*)  d_in[2];
    const float* w_w   = (const float*)d_in[3];
    const int*   idx_w = (const int*)  d_in[4];
    float* out = (float*)d_out;

    const int BC = in_sizes[0] / (H_IN * W_IN);   // 24
    const int Ph = in_sizes[1] / OH_OUT;          // <= 18
    const int Pw = in_sizes[3] / OW_OUT;          // <= 18

    const int nTiles = OH_OUT / R_TILE;           // 45
    size_t smem = (size_t)R_TILE * W_IN * sizeof(float)
                + (size_t)OW_OUT * TPAD * sizeof(short);

    cudaFuncSetAttribute(bicubic_fused6,
                         cudaFuncAttributeMaxDynamicSharedMemorySize,
                         (int)(70 * 1024));

    dim3 grid(BC * nTiles);                       // 1080
    bicubic_fused6<<<grid, NT, smem>>>(
        x, w_h, idx_h, w_w, idx_w, out, Ph, Pw, nTiles);
}